// round 12
// baseline (speedup 1.0000x reference)
#include <cuda_runtime.h>
#include <cuda_bf16.h>
#include <math.h>

// Problem dims
#define BB 1024
#define TT 128
#define EE 300
#define HH 100
#define GG 400     // 4*H
#define VV 50000
#define NB 8       // batches per LSTM CTA
#define NTILES 50  // GG/8 (permuted gate-interleaved layout)
#define KTILES 13  // ceil(HH/8)
#define LSTM_THREADS 576

// Scratch (device globals -- no allocation allowed)
// g_P is stored COLUMN-PERMUTED: permuted col p holds orig col (p&3)*100+(p>>2)
__device__ float g_P[VV * GG];
__device__ float g_out[BB * TT * HH]; // hidden states (52 MB)
__device__ float g_last[BB * HH];
__device__ float g_label[BB * HH];
__device__ float g_q[BB * 6];
__device__ float g_probe;

// ---------------- PTX helpers ----------------
__device__ __forceinline__ unsigned f2tf32(float x) {
    unsigned u;
    asm("cvt.rna.tf32.f32 %0, %1;" : "=r"(u) : "f"(x));
    return u;
}

__device__ __forceinline__ void mma_tf32(float* d, const unsigned* a, const unsigned* b) {
    asm volatile(
        "mma.sync.aligned.m16n8k8.row.col.f32.tf32.tf32.f32 "
        "{%0,%1,%2,%3}, {%4,%5,%6,%7}, {%8,%9}, {%0,%1,%2,%3};"
        : "+f"(d[0]), "+f"(d[1]), "+f"(d[2]), "+f"(d[3])
        : "r"(a[0]), "r"(a[1]), "r"(a[2]), "r"(a[3]), "r"(b[0]), "r"(b[1]));
}

// Rows 8..15 of A are zero padding -> a1,a3 = 0. d[2],d[3] are per-chain junk
// slots (MUST be per-chain: sharing them serializes the HMMA stream).
__device__ __forceinline__ void mma_tf32_half4(float* d, unsigned a0, unsigned a2,
                                               unsigned b0, unsigned b1) {
    asm volatile(
        "mma.sync.aligned.m16n8k8.row.col.f32.tf32.tf32.f32 "
        "{%0,%1,%2,%3}, {%4,%5,%6,%7}, {%8,%9}, {%0,%1,%2,%3};"
        : "+f"(d[0]), "+f"(d[1]), "+f"(d[2]), "+f"(d[3])
        : "r"(a0), "r"(0u), "r"(a2), "r"(0u), "r"(b0), "r"(b1));
}

// ldmatrix: an 8x8 tf32 tile stored as rows of 4 consecutive tf32 (16B) is
// bit-identical to 8x16 b16; m8n8.b16 distribution gives lane 4r+c element
// (r, c) as u32 -> exactly the tf32 mma fragment mapping.
__device__ __forceinline__ void ldsm_x4(unsigned* r, unsigned addr) {
    asm volatile("ldmatrix.sync.aligned.m8n8.x4.shared.b16 {%0,%1,%2,%3}, [%4];"
        : "=r"(r[0]), "=r"(r[1]), "=r"(r[2]), "=r"(r[3]) : "r"(addr));
}
__device__ __forceinline__ void ldsm_x2(unsigned* r, unsigned addr) {
    asm volatile("ldmatrix.sync.aligned.m8n8.x2.shared.b16 {%0,%1}, [%2];"
        : "=r"(r[0]), "=r"(r[1]) : "r"(addr));
}

// HW tanh (sm_75+): single MUFU op, ~2^-11 abs error
__device__ __forceinline__ float tanh_hw(float x) {
    float y;
    asm("tanh.approx.f32 %0, %1;" : "=f"(y) : "f"(x));
    return y;
}
__device__ __forceinline__ float sigm_hw(float x) {
    return fmaf(tanh_hw(0.5f * x), 0.5f, 0.5f);
}

// ---------------------------------------------------------------------------
// Kernel 1: P[v, p] = sum_e emb[v,e]*W_ih[orig(p),e] + bias[orig(p)]
// (unchanged from round 11 -- measured 146us, near its l1tex layout-floor)
// ---------------------------------------------------------------------------
#define A_STRIDE 20
#define B_STRIDE 20
#define NITER 19   // ceil(300/16)

__global__ void gemm_P_kernel(const float* __restrict__ emb,
                              const float* __restrict__ W_ih,
                              const float* __restrict__ b_ih,
                              const float* __restrict__ b_hh) {
    __shared__ float As[2][128 * A_STRIDE];
    __shared__ float Bs[2][64 * B_STRIDE];

    const int m0 = blockIdx.y * 128;
    const int n0 = blockIdx.x * 64;   // permuted-column block
    const int tid = threadIdx.x;
    const int lane = tid & 31;
    const int wid = tid >> 5;
    const int warp_m = wid & 3;
    const int warp_n = wid >> 2;

    float acc[2][4][4];
#pragma unroll
    for (int mt = 0; mt < 2; mt++)
#pragma unroll
        for (int nt = 0; nt < 4; nt++)
#pragma unroll
            for (int c = 0; c < 4; c++) acc[mt][nt][c] = 0.f;

    float4 ra[2], rb;
    const int aq = tid & 3;
    const int am0 = (tid >> 2);
    const int bn = tid >> 2;
    const int gn_p = n0 + bn;
    const int gn_orig = (gn_p & 3) * 100 + (gn_p >> 2);

    const int lr = lane & 7;
    const int lhalf = (lane >> 3) & 1;
    const int lkh = (lane >> 4) & 1;
    const int l4 = lane & 15;
    const int br = l4 & 7;
    const int bkh = (l4 >> 3) & 1;

    auto loadAB = [&](int it) {
        int k0 = it * 16;
#pragma unroll
        for (int i = 0; i < 2; i++) {
            int m = am0 + i * 64;
            int gm = m0 + m;
            int gk = k0 + aq * 4;
            ra[i] = make_float4(0.f, 0.f, 0.f, 0.f);
            if (gm < VV && gk < EE)
                ra[i] = *reinterpret_cast<const float4*>(&emb[gm * EE + gk]);
        }
        int gk = k0 + aq * 4;
        rb = make_float4(0.f, 0.f, 0.f, 0.f);
        if (gn_p < GG && gk < EE)
            rb = *reinterpret_cast<const float4*>(&W_ih[gn_orig * EE + gk]);
    };

    loadAB(0);

    for (int it = 0; it < NITER; it++) {
        const int buf = it & 1;
        *reinterpret_cast<float4*>(&As[buf][am0 * A_STRIDE + aq * 4]) = ra[0];
        *reinterpret_cast<float4*>(&As[buf][(am0 + 64) * A_STRIDE + aq * 4]) = ra[1];
        *reinterpret_cast<float4*>(&Bs[buf][bn * B_STRIDE + aq * 4]) = rb;
        __syncthreads();

        if (it + 1 < NITER) loadAB(it + 1);

        const unsigned aBase = (unsigned)__cvta_generic_to_shared(
            &As[buf][(warp_m * 32 + lhalf * 8 + lr) * A_STRIDE + lkh * 4]);
        const unsigned bBase = (unsigned)__cvta_generic_to_shared(
            &Bs[buf][(warp_n * 32 + br) * B_STRIDE + bkh * 4]);

#pragma unroll
        for (int kt = 0; kt < 2; kt++) {
            unsigned afr[2][4];
            ldsm_x4(afr[0], aBase + kt * 32);
            ldsm_x4(afr[1], aBase + 16 * A_STRIDE * 4 + kt * 32);
            unsigned bfr[4][2];
#pragma unroll
            for (int nt = 0; nt < 4; nt++)
                ldsm_x2(bfr[nt], bBase + nt * 8 * B_STRIDE * 4 + kt * 32);
#pragma unroll
            for (int mt = 0; mt < 2; mt++)
#pragma unroll
                for (int nt = 0; nt < 4; nt++)
                    mma_tf32(acc[mt][nt], afr[mt], bfr[nt]);
        }
        __syncthreads();
    }

#pragma unroll
    for (int nt = 0; nt < 4; nt++) {
        int col = n0 + warp_n * 32 + nt * 8 + (lane & 3) * 2;   // permuted
        if (col >= GG) continue;
        int o0 = (col & 3) * 100 + (col >> 2);
        int o1 = ((col + 1) & 3) * 100 + ((col + 1) >> 2);
        float ba = b_ih[o0] + b_hh[o0];
        float bb = b_ih[o1] + b_hh[o1];
#pragma unroll
        for (int mt = 0; mt < 2; mt++) {
            int row0 = m0 + warp_m * 32 + mt * 16 + (lane >> 2);
            if (row0 < VV) {
                float2 v = make_float2(acc[mt][nt][0] + ba, acc[mt][nt][1] + bb);
                *reinterpret_cast<float2*>(&g_P[(size_t)row0 * GG + col]) = v;
            }
            int row1 = row0 + 8;
            if (row1 < VV) {
                float2 v = make_float2(acc[mt][nt][2] + ba, acc[mt][nt][3] + bb);
                *reinterpret_cast<float2*>(&g_P[(size_t)row1 * GG + col]) = v;
            }
        }
    }
}

// ---------------------------------------------------------------------------
// Kernel 2: label_vec[b] = emb[label_word_id[b]] @ ll_W^T + ll_b
// ---------------------------------------------------------------------------
__global__ void label_kernel(const int* __restrict__ label_word_id,
                             const float* __restrict__ emb,
                             const float* __restrict__ ll_W,
                             const float* __restrict__ ll_b) {
    __shared__ float row[EE];
    const int b = blockIdx.x;
    const int w = label_word_id[b];
    for (int e = threadIdx.x; e < EE; e += blockDim.x) row[e] = emb[w * EE + e];
    __syncthreads();
    const int j = threadIdx.x;
    if (j < HH) {
        float s = ll_b[j];
        const float* wr = &ll_W[j * EE];
        for (int e = 0; e < EE; e++) s += row[e] * wr[e];
        g_label[b * HH + j] = s;
    }
}

__global__ void probe_kernel() {
    if (threadIdx.x == 0) g_probe = 0.f;
}

// ---------------------------------------------------------------------------
// Kernel 3: LSTM recurrence. 128 CTAs x NB=8, 576 threads (18 warps).
//  - W_hh frags tiles 0,1 in registers; 3rd tile streams from smem
//  - SPLIT accumulation chains (kt 0-6 / 7-12) -> RAW depth 13 -> 7,
//    6 independent HMMA chains per warp
//  - all loop-invariant addressing hoisted out of the t-loop
// ---------------------------------------------------------------------------
__global__ void __launch_bounds__(LSTM_THREADS, 1)
lstm_kernel(const int* __restrict__ word_id,
            const int* __restrict__ sen_len,
            const float* __restrict__ W_hh) {
    __shared__ unsigned Hf[2][KTILES * 64];
    __shared__ unsigned Bs3[14 * KTILES * 64];   // 3rd-tile B frags for 14 warps
    __shared__ int rows[2][NB];
    __shared__ int senl[NB];

    const int tid = threadIdx.x;
    const int b0 = blockIdx.x * NB;
    const int lane = tid & 31;
    const int w = tid >> 5;
    const int nb = lane >> 2;
    const int cl2 = 2 * (lane & 3);

    const int ntc = (w == 12 || w == 13 || w == 16 || w == 17) ? 2 : 3;
    const int base = 3 * w - (w > 12) - (w > 13) - (w > 16) - (w > 17);
    const int slot3 = (w < 12) ? w : w - 2;
    const unsigned* Bs3w = &Bs3[slot3 * KTILES * 64];

    unsigned Breg[2][KTILES][2];
#pragma unroll
    for (int i = 0; i < 2; i++) {
        int nt = base + i;
        int n_perm = nt * 8 + (lane >> 2);
        int orig_n = (n_perm & 3) * 100 + (n_perm >> 2);
        const float* wr = &W_hh[orig_n * HH];
#pragma unroll
        for (int kt = 0; kt < KTILES; kt++) {
            int k0 = kt * 8 + (lane & 3);
            int k1 = k0 + 4;
            Breg[i][kt][0] = (k0 < HH) ? f2tf32(wr[k0]) : 0u;
            Breg[i][kt][1] = (k1 < HH) ? f2tf32(wr[k1]) : 0u;
        }
    }
    if (ntc == 3) {
        int nt = base + 2;
        int n_perm = nt * 8 + (lane >> 2);
        int orig_n = (n_perm & 3) * 100 + (n_perm >> 2);
        const float* wr = &W_hh[orig_n * HH];
        for (int kt = 0; kt < KTILES; kt++) {
            int k0 = kt * 8 + (lane & 3);
            int k1 = k0 + 4;
            unsigned v0 = (k0 < HH) ? f2tf32(wr[k0]) : 0u;
            unsigned v1 = (k1 < HH) ? f2tf32(wr[k1]) : 0u;
            Bs3[slot3 * KTILES * 64 + kt * 64 + lane * 2]     = v0;
            Bs3[slot3 * KTILES * 64 + kt * 64 + lane * 2 + 1] = v1;
        }
    }

    for (int idx = tid; idx < KTILES * 64; idx += LSTM_THREADS) Hf[0][idx] = 0u;
    if (tid < NB) {
        senl[tid] = sen_len[b0 + tid];
        rows[0][tid] = word_id[(b0 + tid) * TT];
    }

    // ---- hoist loop-invariant activation addressing ----
    const bool odd = (lane & 1);
    const int jsel = (lane >> 1) & 1;
    const int sl = sen_len[b0 + nb];      // this lane's batch sen_len
    int   jb[2];        // j per bundle
    bool  wrv[2];       // write-valid per bundle
    unsigned hfoff[2];  // Hf write offset within a buffer
    float* outp[2];     // running g_out pointer (advances by HH per step)
    float* lastp[2];
#pragma unroll
    for (int bundle = 0; bundle < 2; bundle++) {
        const int iA = (bundle == 0) ? 0 : 2;
        const int iB = (bundle == 0) ? 1 : 2;
        int nt = base + (odd ? iB : iA);
        int j = 2 * nt + jsel;
        jb[bundle] = j;
        wrv[bundle] = !(iA == iB && odd);
        int jl = j & 7, kt = j >> 3;
        hfoff[bundle] = (kt * 32 + ((nb << 2) | (jl & 3))) * 2 + ((jl >> 2) & 1);
        outp[bundle] = &g_out[((size_t)(b0 + nb) * TT) * HH + j];
        lastp[bundle] = &g_last[(b0 + nb) * HH + j];
    }
    __syncthreads();

    float cst[2] = {0.f, 0.f};

    for (int t = 0; t < TT; t++) {
        const int buf = t & 1;

        float2 pv[3];
        {
            const float* Prow = &g_P[(size_t)rows[buf][nb] * GG];
            pv[0] = *reinterpret_cast<const float2*>(&Prow[(base + 0) * 8 + cl2]);
            pv[1] = *reinterpret_cast<const float2*>(&Prow[(base + 1) * 8 + cl2]);
            if (ntc == 3)
                pv[2] = *reinterpret_cast<const float2*>(&Prow[(base + 2) * 8 + cl2]);
        }

        // split chains: [tile][half][4]
        float acc[3][2][4];
#pragma unroll
        for (int i = 0; i < 3; i++)
#pragma unroll
            for (int hs = 0; hs < 2; hs++) {
                acc[i][hs][0] = 0.f; acc[i][hs][1] = 0.f;
                acc[i][hs][2] = 0.f; acc[i][hs][3] = 0.f;
            }

#pragma unroll
        for (int kt = 0; kt < KTILES; kt++) {
            const int hs = (kt < 7) ? 0 : 1;
            uint2 hv = *reinterpret_cast<const uint2*>(&Hf[buf][(kt * 32 + lane) * 2]);
            mma_tf32_half4(acc[0][hs], hv.x, hv.y, Breg[0][kt][0], Breg[0][kt][1]);
            mma_tf32_half4(acc[1][hs], hv.x, hv.y, Breg[1][kt][0], Breg[1][kt][1]);
            if (ntc == 3) {
                uint2 bv = *reinterpret_cast<const uint2*>(&Bs3w[kt * 64 + lane * 2]);
                mma_tf32_half4(acc[2][hs], hv.x, hv.y, bv.x, bv.y);
            }
        }

        // combine halves + P
        float r[3][2];
        r[0][0] = acc[0][0][0] + acc[0][1][0] + pv[0].x;
        r[0][1] = acc[0][0][1] + acc[0][1][1] + pv[0].y;
        r[1][0] = acc[1][0][0] + acc[1][1][0] + pv[1].x;
        r[1][1] = acc[1][0][1] + acc[1][1][1] + pv[1].y;
        if (ntc == 3) {
            r[2][0] = acc[2][0][0] + acc[2][1][0] + pv[2].x;
            r[2][1] = acc[2][0][1] + acc[2][1][1] + pv[2].y;
        }

#pragma unroll
        for (int bundle = 0; bundle < 2; bundle++) {
            if (bundle == 1 && ntc < 3) break;
            const int iA = (bundle == 0) ? 0 : 2;
            const int iB = (bundle == 0) ? 1 : 2;
            float xA0 = __shfl_xor_sync(0xffffffffu, r[iA][0], 1);
            float xA1 = __shfl_xor_sync(0xffffffffu, r[iA][1], 1);
            float xB0 = __shfl_xor_sync(0xffffffffu, r[iB][0], 1);
            float xB1 = __shfl_xor_sync(0xffffffffu, r[iB][1], 1);
            float gi = odd ? xB0 : r[iA][0];
            float gf = odd ? xB1 : r[iA][1];
            float gg = odd ? r[iB][0] : xA0;
            float go = odd ? r[iB][1] : xA1;

            float si = sigm_hw(gi);
            float sf = sigm_hw(gf);
            float so = sigm_hw(go);
            float sg = tanh_hw(gg);
            float cv = sf * cst[bundle] + si * sg;
            cst[bundle] = cv;
            float h = so * tanh_hw(cv);

            if (wrv[bundle]) {
                Hf[1 - buf][hfoff[bundle]] = f2tf32(h);
                outp[bundle][0] = h;
                if (t == sl - 1) lastp[bundle][0] = h;
            }
        }
        outp[0] += HH;
        outp[1] += HH;

        if (tid < NB && t + 1 < TT)
            rows[1 - buf][tid] = word_id[(b0 + tid) * TT + t + 1];
        __syncthreads();
    }
}

// ---------------------------------------------------------------------------
// Kernel 4: per-batch epilogue: scores, top-4, pos, per_neg, out_f, l_rep, q.
// ---------------------------------------------------------------------------
__global__ void catch_kernel(const int* __restrict__ sen_len,
                             const float* __restrict__ lin_W,
                             const float* __restrict__ lin_b,
                             float* __restrict__ dout) {
    __shared__ float label_s[HH];
    __shared__ float last_s[HH];
    __shared__ float scores[TT];
    __shared__ float red_v[TT];
    __shared__ int   red_i[TT];
    __shared__ float topv[4];
    __shared__ int   topi[4];
    __shared__ float pos_s[HH];
    __shared__ float pneg_s[HH];

    const int b = blockIdx.x;
    const int tid = threadIdx.x;
    const int L = sen_len[b];

    if (tid < HH) {
        label_s[tid] = g_label[b * HH + tid];
        last_s[tid]  = g_last[b * HH + tid];
    }
    __syncthreads();

    {
        float s;
        if (tid < L) {
            s = 0.f;
            const float* o = &g_out[((size_t)b * TT + tid) * HH];
            for (int j = 0; j < HH; j++) s += o[j] * label_s[j];
        } else {
            s = -1e30f;
        }
        scores[tid] = s;
    }
    __syncthreads();

    for (int k = 0; k < 4; k++) {
        red_v[tid] = scores[tid];
        red_i[tid] = tid;
        __syncthreads();
        for (int off = TT / 2; off > 0; off >>= 1) {
            if (tid < off) {
                float v2 = red_v[tid + off];
                int   i2 = red_i[tid + off];
                if (v2 > red_v[tid] || (v2 == red_v[tid] && i2 < red_i[tid])) {
                    red_v[tid] = v2;
                    red_i[tid] = i2;
                }
            }
            __syncthreads();
        }
        if (tid == 0) {
            topv[k] = red_v[0];
            topi[k] = red_i[0];
            scores[red_i[0]] = -1e30f;
        }
        __syncthreads();
    }

    if (tid < HH) {
        float p = 0.f;
#pragma unroll
        for (int k = 0; k < 4; k++)
            p += g_out[((size_t)b * TT + topi[k]) * HH + tid] * topv[k];
        pos_s[tid] = p;

        float s = 0.f;
        int i0 = topi[0], i1 = topi[1], i2 = topi[2], i3 = topi[3];
        for (int t = 0; t < L; t++) {
            if (t == i0 || t == i1 || t == i2 || t == i3) continue;
            s += g_out[((size_t)b * TT + t) * HH + tid];
        }
        pneg_s[tid] = s;
    }
    __syncthreads();

    if (tid < 6) {
        float bo = lin_b[tid];
        float o = bo, l = bo, q = 0.f;
        const float* wv = &lin_W[tid * HH];
        for (int j = 0; j < HH; j++) {
            float wj = wv[j];
            o += last_s[j] * wj;
            l += pos_s[j] * wj;
            q += pneg_s[j] * wj;
        }
        dout[b * 6 + tid] = o;
        dout[BB * 6 + b * 6 + tid] = l;
        g_q[b * 6 + tid] = q;
    }
}

// ---------------------------------------------------------------------------
// Kernel 5: r_rep = cumsum over batch of q + lin_b (warp-parallel scan).
// ---------------------------------------------------------------------------
__global__ void scan_kernel(const float* __restrict__ lin_b,
                            float* __restrict__ dout) {
    const int w = threadIdx.x >> 5;
    const int l = threadIdx.x & 31;
    if (w >= 6) return;
    float run = lin_b[w];
    for (int c0 = 0; c0 < BB; c0 += 32) {
        float v = g_q[(c0 + l) * 6 + w];
#pragma unroll
        for (int off = 1; off < 32; off <<= 1) {
            float u = __shfl_up_sync(0xffffffff, v, off);
            if (l >= off) v += u;
        }
        dout[2 * BB * 6 + (c0 + l) * 6 + w] = run + v;
        run += __shfl_sync(0xffffffff, v, 31);
    }
}

// ---------------------------------------------------------------------------
extern "C" void kernel_launch(void* const* d_in, const int* in_sizes, int n_in,
                              void* d_out, int out_size) {
    const int*   word_id       = (const int*)d_in[0];
    const int*   sen_len       = (const int*)d_in[1];
    const int*   label_word_id = (const int*)d_in[2];
    const float* emb           = (const float*)d_in[3];
    const float* W_ih          = (const float*)d_in[4];
    const float* W_hh          = (const float*)d_in[5];
    const float* b_ih          = (const float*)d_in[6];
    const float* b_hh          = (const float*)d_in[7];
    const float* lin_W         = (const float*)d_in[8];
    const float* lin_b         = (const float*)d_in[9];
    const float* ll_W          = (const float*)d_in[10];
    const float* ll_b          = (const float*)d_in[11];
    float* out = (float*)d_out;

    dim3 ggrid((GG + 63) / 64, (VV + 127) / 128);   // n fastest -> A slab L2 reuse
    // ncu captures launch index 3 -> lstm there this round (gemm runs first).
    gemm_P_kernel<<<ggrid, 256>>>(emb, W_ih, b_ih, b_hh);            // idx 0
    label_kernel<<<BB, 128>>>(label_word_id, emb, ll_W, ll_b);       // idx 1
    probe_kernel<<<1, 32>>>();                                       // idx 2
    lstm_kernel<<<BB / NB, LSTM_THREADS>>>(word_id, sen_len, W_hh);  // idx 3 (profiled)
    catch_kernel<<<BB, 128>>>(sen_len, lin_W, lin_b, out);           // idx 4
    scan_kernel<<<1, 192>>>(lin_b, out);                             // idx 5
}

// round 14
// speedup vs baseline: 1.2715x; 1.2715x over previous
#include <cuda_runtime.h>
#include <cuda_bf16.h>
#include <math.h>

// Problem dims
#define BB 1024
#define TT 128
#define EE 300
#define HH 100
#define GG 400     // 4*H
#define VV 50000
#define NB 8       // batches per LSTM CTA
#define NTILES 50  // GG/8 (permuted gate-interleaved layout)
#define KT16 7     // ceil(HH/16) bf16 k-tiles
#define LSTM_THREADS 576

// Scratch (device globals -- no allocation allowed)
// g_P is stored COLUMN-PERMUTED: permuted col p holds orig col (p&3)*100+(p>>2)
__device__ float g_P[VV * GG];
__device__ float g_out[BB * TT * HH]; // hidden states (52 MB)
__device__ float g_last[BB * HH];
__device__ float g_label[BB * HH];
__device__ float g_q[BB * 6];
__device__ float g_probe;

// ---------------- PTX helpers ----------------
__device__ __forceinline__ unsigned f2tf32(float x) {
    unsigned u;
    asm("cvt.rna.tf32.f32 %0, %1;" : "=r"(u) : "f"(x));
    return u;
}

__device__ __forceinline__ unsigned pack_bf16(float lo, float hi) {
    __nv_bfloat162 v = __floats2bfloat162_rn(lo, hi);   // x=lo(low half), y=hi
    return *reinterpret_cast<unsigned*>(&v);
}

__device__ __forceinline__ void mma_tf32(float* d, const unsigned* a, const unsigned* b) {
    asm volatile(
        "mma.sync.aligned.m16n8k8.row.col.f32.tf32.tf32.f32 "
        "{%0,%1,%2,%3}, {%4,%5,%6,%7}, {%8,%9}, {%0,%1,%2,%3};"
        : "+f"(d[0]), "+f"(d[1]), "+f"(d[2]), "+f"(d[3])
        : "r"(a[0]), "r"(a[1]), "r"(a[2]), "r"(a[3]), "r"(b[0]), "r"(b[1]));
}

// bf16 m16n8k16; A rows 8..15 are zero padding -> a1,a3 = 0. d[2],d[3] junk.
__device__ __forceinline__ void mma_bf16_half4(float* d, unsigned a0, unsigned a2,
                                               unsigned b0, unsigned b1) {
    asm volatile(
        "mma.sync.aligned.m16n8k16.row.col.f32.bf16.bf16.f32 "
        "{%0,%1,%2,%3}, {%4,%5,%6,%7}, {%8,%9}, {%0,%1,%2,%3};"
        : "+f"(d[0]), "+f"(d[1]), "+f"(d[2]), "+f"(d[3])
        : "r"(a0), "r"(0u), "r"(a2), "r"(0u), "r"(b0), "r"(b1));
}

// ldmatrix (tf32-as-b16 trick) for gemm_P
__device__ __forceinline__ void ldsm_x4(unsigned* r, unsigned addr) {
    asm volatile("ldmatrix.sync.aligned.m8n8.x4.shared.b16 {%0,%1,%2,%3}, [%4];"
        : "=r"(r[0]), "=r"(r[1]), "=r"(r[2]), "=r"(r[3]) : "r"(addr));
}
__device__ __forceinline__ void ldsm_x2(unsigned* r, unsigned addr) {
    asm volatile("ldmatrix.sync.aligned.m8n8.x2.shared.b16 {%0,%1}, [%2];"
        : "=r"(r[0]), "=r"(r[1]) : "r"(addr));
}

// HW tanh (sm_75+)
__device__ __forceinline__ float tanh_hw(float x) {
    float y;
    asm("tanh.approx.f32 %0, %1;" : "=f"(y) : "f"(x));
    return y;
}
__device__ __forceinline__ float sigm_hw(float x) {
    return fmaf(tanh_hw(0.5f * x), 0.5f, 0.5f);
}

// ---------------------------------------------------------------------------
// Kernel 1: P[v, p] = sum_e emb[v,e]*W_ih[orig(p),e] + bias[orig(p)]
// (unchanged from round 11 -- measured 146us)
// ---------------------------------------------------------------------------
#define A_STRIDE 20
#define B_STRIDE 20
#define NITER 19   // ceil(300/16)

__global__ void gemm_P_kernel(const float* __restrict__ emb,
                              const float* __restrict__ W_ih,
                              const float* __restrict__ b_ih,
                              const float* __restrict__ b_hh) {
    __shared__ float As[2][128 * A_STRIDE];
    __shared__ float Bs[2][64 * B_STRIDE];

    const int m0 = blockIdx.y * 128;
    const int n0 = blockIdx.x * 64;   // permuted-column block
    const int tid = threadIdx.x;
    const int lane = tid & 31;
    const int wid = tid >> 5;
    const int warp_m = wid & 3;
    const int warp_n = wid >> 2;

    float acc[2][4][4];
#pragma unroll
    for (int mt = 0; mt < 2; mt++)
#pragma unroll
        for (int nt = 0; nt < 4; nt++)
#pragma unroll
            for (int c = 0; c < 4; c++) acc[mt][nt][c] = 0.f;

    float4 ra[2], rb;
    const int aq = tid & 3;
    const int am0 = (tid >> 2);
    const int bn = tid >> 2;
    const int gn_p = n0 + bn;
    const int gn_orig = (gn_p & 3) * 100 + (gn_p >> 2);

    const int lr = lane & 7;
    const int lhalf = (lane >> 3) & 1;
    const int lkh = (lane >> 4) & 1;
    const int l4 = lane & 15;
    const int br = l4 & 7;
    const int bkh = (l4 >> 3) & 1;

    auto loadAB = [&](int it) {
        int k0 = it * 16;
#pragma unroll
        for (int i = 0; i < 2; i++) {
            int m = am0 + i * 64;
            int gm = m0 + m;
            int gk = k0 + aq * 4;
            ra[i] = make_float4(0.f, 0.f, 0.f, 0.f);
            if (gm < VV && gk < EE)
                ra[i] = *reinterpret_cast<const float4*>(&emb[gm * EE + gk]);
        }
        int gk = k0 + aq * 4;
        rb = make_float4(0.f, 0.f, 0.f, 0.f);
        if (gn_p < GG && gk < EE)
            rb = *reinterpret_cast<const float4*>(&W_ih[gn_orig * EE + gk]);
    };

    loadAB(0);

    for (int it = 0; it < NITER; it++) {
        const int buf = it & 1;
        *reinterpret_cast<float4*>(&As[buf][am0 * A_STRIDE + aq * 4]) = ra[0];
        *reinterpret_cast<float4*>(&As[buf][(am0 + 64) * A_STRIDE + aq * 4]) = ra[1];
        *reinterpret_cast<float4*>(&Bs[buf][bn * B_STRIDE + aq * 4]) = rb;
        __syncthreads();

        if (it + 1 < NITER) loadAB(it + 1);

        const unsigned aBase = (unsigned)__cvta_generic_to_shared(
            &As[buf][(warp_m * 32 + lhalf * 8 + lr) * A_STRIDE + lkh * 4]);
        const unsigned bBase = (unsigned)__cvta_generic_to_shared(
            &Bs[buf][(warp_n * 32 + br) * B_STRIDE + bkh * 4]);

#pragma unroll
        for (int kt = 0; kt < 2; kt++) {
            unsigned afr[2][4];
            ldsm_x4(afr[0], aBase + kt * 32);
            ldsm_x4(afr[1], aBase + 16 * A_STRIDE * 4 + kt * 32);
            unsigned bfr[4][2];
#pragma unroll
            for (int nt = 0; nt < 4; nt++)
                ldsm_x2(bfr[nt], bBase + nt * 8 * B_STRIDE * 4 + kt * 32);
#pragma unroll
            for (int mt = 0; mt < 2; mt++)
#pragma unroll
                for (int nt = 0; nt < 4; nt++)
                    mma_tf32(acc[mt][nt], afr[mt], bfr[nt]);
        }
        __syncthreads();
    }

#pragma unroll
    for (int nt = 0; nt < 4; nt++) {
        int col = n0 + warp_n * 32 + nt * 8 + (lane & 3) * 2;   // permuted
        if (col >= GG) continue;
        int o0 = (col & 3) * 100 + (col >> 2);
        int o1 = ((col + 1) & 3) * 100 + ((col + 1) >> 2);
        float ba = b_ih[o0] + b_hh[o0];
        float bb = b_ih[o1] + b_hh[o1];
#pragma unroll
        for (int mt = 0; mt < 2; mt++) {
            int row0 = m0 + warp_m * 32 + mt * 16 + (lane >> 2);
            if (row0 < VV) {
                float2 v = make_float2(acc[mt][nt][0] + ba, acc[mt][nt][1] + bb);
                *reinterpret_cast<float2*>(&g_P[(size_t)row0 * GG + col]) = v;
            }
            int row1 = row0 + 8;
            if (row1 < VV) {
                float2 v = make_float2(acc[mt][nt][2] + ba, acc[mt][nt][3] + bb);
                *reinterpret_cast<float2*>(&g_P[(size_t)row1 * GG + col]) = v;
            }
        }
    }
}

// ---------------------------------------------------------------------------
// Kernel 2: label_vec[b] = emb[label_word_id[b]] @ ll_W^T + ll_b
// ---------------------------------------------------------------------------
__global__ void label_kernel(const int* __restrict__ label_word_id,
                             const float* __restrict__ emb,
                             const float* __restrict__ ll_W,
                             const float* __restrict__ ll_b) {
    __shared__ float row[EE];
    const int b = blockIdx.x;
    const int w = label_word_id[b];
    for (int e = threadIdx.x; e < EE; e += blockDim.x) row[e] = emb[w * EE + e];
    __syncthreads();
    const int j = threadIdx.x;
    if (j < HH) {
        float s = ll_b[j];
        const float* wr = &ll_W[j * EE];
        for (int e = 0; e < EE; e++) s += row[e] * wr[e];
        g_label[b * HH + j] = s;
    }
}

__global__ void probe_kernel() {
    if (threadIdx.x == 0) g_probe = 0.f;
}

// ---------------------------------------------------------------------------
// Kernel 3: LSTM recurrence on bf16 m16n8k16. 128 CTAs x NB=8, 576 threads.
//  - K-tiles 13 -> 7, MMAs/warp/step 39 -> 21, bf16 HMMA full-rate
//  - ALL W_hh fragments register-resident (42 regs; Bs3 smem deleted)
//  - h stored bf16 in A-fragment layout (u32 = 2 consecutive k); pad k zeros
//  - activations fp32; P gather fp32; one __syncthreads per step.
// Hf layout: [buf][kt*64 + lane*2 + half] (half: 0 = k 0-7 pair set, 1 = k 8-15)
// ---------------------------------------------------------------------------
__global__ void __launch_bounds__(LSTM_THREADS, 1)
lstm_kernel(const int* __restrict__ word_id,
            const int* __restrict__ sen_len,
            const float* __restrict__ W_hh) {
    __shared__ unsigned Hf[2][KT16 * 64];
    __shared__ int rows[2][NB];
    __shared__ int senl[NB];

    const int tid = threadIdx.x;
    const int b0 = blockIdx.x * NB;
    const int lane = tid & 31;
    const int w = tid >> 5;
    const int nb = lane >> 2;
    const int cl2 = 2 * (lane & 3);

    const int ntc = (w == 12 || w == 13 || w == 16 || w == 17) ? 2 : 3;
    const int base = 3 * w - (w > 12) - (w > 13) - (w > 16) - (w > 17);

    // ---- one-time: ALL W_hh B-fragments into registers (bf16, permuted cols)
    unsigned Breg[3][KT16][2];
#pragma unroll
    for (int i = 0; i < 3; i++) {
        int nt = base + i;
        int n_perm = nt * 8 + (lane >> 2);
        int orig_n = (n_perm & 3) * 100 + (n_perm >> 2);
        const float* wr = &W_hh[orig_n * HH];
#pragma unroll
        for (int kt = 0; kt < KT16; kt++) {
            if (i < ntc) {
                int k0 = kt * 16 + (lane & 3) * 2;
                float l0 = (k0 < HH) ? wr[k0] : 0.f;
                float h0 = (k0 + 1 < HH) ? wr[k0 + 1] : 0.f;
                Breg[i][kt][0] = pack_bf16(l0, h0);
                int k8 = k0 + 8;
                float l1 = (k8 < HH) ? wr[k8] : 0.f;
                float h1 = (k8 + 1 < HH) ? wr[k8 + 1] : 0.f;
                Breg[i][kt][1] = pack_bf16(l1, h1);
            } else {
                Breg[i][kt][0] = 0u;
                Breg[i][kt][1] = 0u;
            }
        }
    }

    // zero BOTH Hf buffers (k-pad 100..111 must stay zero forever)
    for (int idx = tid; idx < 2 * KT16 * 64; idx += LSTM_THREADS)
        (&Hf[0][0])[idx] = 0u;
    if (tid < NB) {
        senl[tid] = sen_len[b0 + tid];
        rows[0][tid] = word_id[(b0 + tid) * TT];
    }

    // ---- hoist loop-invariant activation addressing ----
    const bool odd = (lane & 1);
    const int jsel = (lane >> 1) & 1;
    const int sl = sen_len[b0 + nb];
    bool  wrv[2];
    int   hfhw[2];     // half-word index within an Hf buffer
    float* outp[2];
    float* lastp[2];
#pragma unroll
    for (int bundle = 0; bundle < 2; bundle++) {
        const int iA = (bundle == 0) ? 0 : 2;
        const int iB = (bundle == 0) ? 1 : 2;
        int nt = base + (odd ? iB : iA);
        int j = 2 * nt + jsel;
        wrv[bundle] = !(iA == iB && odd);
        // A-frag slot for (batch nb, k=j): kt=j/16, half=(j%16)/8, c=(j%8)/2, hi=j&1
        int kt = j >> 4, half = (j >> 3) & 1, c = (j & 7) >> 1, hi = j & 1;
        hfhw[bundle] = (kt * 64 + (nb * 4 + c) * 2 + half) * 2 + hi;
        outp[bundle] = &g_out[((size_t)(b0 + nb) * TT) * HH + j];
        lastp[bundle] = &g_last[(b0 + nb) * HH + j];
    }
    __syncthreads();

    float cst[2] = {0.f, 0.f};

    for (int t = 0; t < TT; t++) {
        const int buf = t & 1;

        float2 pv[3];
        {
            const float* Prow = &g_P[(size_t)rows[buf][nb] * GG];
            pv[0] = *reinterpret_cast<const float2*>(&Prow[(base + 0) * 8 + cl2]);
            pv[1] = *reinterpret_cast<const float2*>(&Prow[(base + 1) * 8 + cl2]);
            if (ntc == 3)
                pv[2] = *reinterpret_cast<const float2*>(&Prow[(base + 2) * 8 + cl2]);
        }

        float acc[3][4];
#pragma unroll
        for (int i = 0; i < 3; i++) {
            acc[i][0] = 0.f; acc[i][1] = 0.f; acc[i][2] = 0.f; acc[i][3] = 0.f;
        }

#pragma unroll
        for (int kt = 0; kt < KT16; kt++) {
            uint2 hv = *reinterpret_cast<const uint2*>(&Hf[buf][kt * 64 + lane * 2]);
            mma_bf16_half4(acc[0], hv.x, hv.y, Breg[0][kt][0], Breg[0][kt][1]);
            mma_bf16_half4(acc[1], hv.x, hv.y, Breg[1][kt][0], Breg[1][kt][1]);
            if (ntc == 3)
                mma_bf16_half4(acc[2], hv.x, hv.y, Breg[2][kt][0], Breg[2][kt][1]);
        }
        float r[3][2];
        r[0][0] = acc[0][0] + pv[0].x;  r[0][1] = acc[0][1] + pv[0].y;
        r[1][0] = acc[1][0] + pv[1].x;  r[1][1] = acc[1][1] + pv[1].y;
        if (ntc == 3) { r[2][0] = acc[2][0] + pv[2].x;  r[2][1] = acc[2][1] + pv[2].y; }

#pragma unroll
        for (int bundle = 0; bundle < 2; bundle++) {
            if (bundle == 1 && ntc < 3) break;
            const int iA = (bundle == 0) ? 0 : 2;
            const int iB = (bundle == 0) ? 1 : 2;
            float xA0 = __shfl_xor_sync(0xffffffffu, r[iA][0], 1);
            float xA1 = __shfl_xor_sync(0xffffffffu, r[iA][1], 1);
            float xB0 = __shfl_xor_sync(0xffffffffu, r[iB][0], 1);
            float xB1 = __shfl_xor_sync(0xffffffffu, r[iB][1], 1);
            float gi = odd ? xB0 : r[iA][0];
            float gf = odd ? xB1 : r[iA][1];
            float gg = odd ? r[iB][0] : xA0;
            float go = odd ? r[iB][1] : xA1;

            float si = sigm_hw(gi);
            float sf = sigm_hw(gf);
            float so = sigm_hw(go);
            float sg = tanh_hw(gg);
            float cv = sf * cst[bundle] + si * sg;
            cst[bundle] = cv;
            float h = so * tanh_hw(cv);

            if (wrv[bundle]) {
                reinterpret_cast<__nv_bfloat16*>(&Hf[1 - buf][0])[hfhw[bundle]] =
                    __float2bfloat16_rn(h);
                outp[bundle][0] = h;
                if (t == sl - 1) lastp[bundle][0] = h;
            }
        }
        outp[0] += HH;
        outp[1] += HH;

        if (tid < NB && t + 1 < TT)
            rows[1 - buf][tid] = word_id[(b0 + tid) * TT + t + 1];
        __syncthreads();
    }
}

// ---------------------------------------------------------------------------
// Kernel 4: per-batch epilogue: scores, top-4, pos, per_neg, out_f, l_rep, q.
// ---------------------------------------------------------------------------
__global__ void catch_kernel(const int* __restrict__ sen_len,
                             const float* __restrict__ lin_W,
                             const float* __restrict__ lin_b,
                             float* __restrict__ dout) {
    __shared__ float label_s[HH];
    __shared__ float last_s[HH];
    __shared__ float scores[TT];
    __shared__ float red_v[TT];
    __shared__ int   red_i[TT];
    __shared__ float topv[4];
    __shared__ int   topi[4];
    __shared__ float pos_s[HH];
    __shared__ float pneg_s[HH];

    const int b = blockIdx.x;
    const int tid = threadIdx.x;
    const int L = sen_len[b];

    if (tid < HH) {
        label_s[tid] = g_label[b * HH + tid];
        last_s[tid]  = g_last[b * HH + tid];
    }
    __syncthreads();

    {
        float s;
        if (tid < L) {
            s = 0.f;
            const float* o = &g_out[((size_t)b * TT + tid) * HH];
            for (int j = 0; j < HH; j++) s += o[j] * label_s[j];
        } else {
            s = -1e30f;
        }
        scores[tid] = s;
    }
    __syncthreads();

    for (int k = 0; k < 4; k++) {
        red_v[tid] = scores[tid];
        red_i[tid] = tid;
        __syncthreads();
        for (int off = TT / 2; off > 0; off >>= 1) {
            if (tid < off) {
                float v2 = red_v[tid + off];
                int   i2 = red_i[tid + off];
                if (v2 > red_v[tid] || (v2 == red_v[tid] && i2 < red_i[tid])) {
                    red_v[tid] = v2;
                    red_i[tid] = i2;
                }
            }
            __syncthreads();
        }
        if (tid == 0) {
            topv[k] = red_v[0];
            topi[k] = red_i[0];
            scores[red_i[0]] = -1e30f;
        }
        __syncthreads();
    }

    if (tid < HH) {
        float p = 0.f;
#pragma unroll
        for (int k = 0; k < 4; k++)
            p += g_out[((size_t)b * TT + topi[k]) * HH + tid] * topv[k];
        pos_s[tid] = p;

        float s = 0.f;
        int i0 = topi[0], i1 = topi[1], i2 = topi[2], i3 = topi[3];
        for (int t = 0; t < L; t++) {
            if (t == i0 || t == i1 || t == i2 || t == i3) continue;
            s += g_out[((size_t)b * TT + t) * HH + tid];
        }
        pneg_s[tid] = s;
    }
    __syncthreads();

    if (tid < 6) {
        float bo = lin_b[tid];
        float o = bo, l = bo, q = 0.f;
        const float* wv = &lin_W[tid * HH];
        for (int j = 0; j < HH; j++) {
            float wj = wv[j];
            o += last_s[j] * wj;
            l += pos_s[j] * wj;
            q += pneg_s[j] * wj;
        }
        dout[b * 6 + tid] = o;
        dout[BB * 6 + b * 6 + tid] = l;
        g_q[b * 6 + tid] = q;
    }
}

// ---------------------------------------------------------------------------
// Kernel 5: r_rep = cumsum over batch of q + lin_b (warp-parallel scan).
// ---------------------------------------------------------------------------
__global__ void scan_kernel(const float* __restrict__ lin_b,
                            float* __restrict__ dout) {
    const int w = threadIdx.x >> 5;
    const int l = threadIdx.x & 31;
    if (w >= 6) return;
    float run = lin_b[w];
    for (int c0 = 0; c0 < BB; c0 += 32) {
        float v = g_q[(c0 + l) * 6 + w];
#pragma unroll
        for (int off = 1; off < 32; off <<= 1) {
            float u = __shfl_up_sync(0xffffffff, v, off);
            if (l >= off) v += u;
        }
        dout[2 * BB * 6 + (c0 + l) * 6 + w] = run + v;
        run += __shfl_sync(0xffffffff, v, 31);
    }
}

// ---------------------------------------------------------------------------
extern "C" void kernel_launch(void* const* d_in, const int* in_sizes, int n_in,
                              void* d_out, int out_size) {
    const int*   word_id       = (const int*)d_in[0];
    const int*   sen_len       = (const int*)d_in[1];
    const int*   label_word_id = (const int*)d_in[2];
    const float* emb           = (const float*)d_in[3];
    const float* W_ih          = (const float*)d_in[4];
    const float* W_hh          = (const float*)d_in[5];
    const float* b_ih          = (const float*)d_in[6];
    const float* b_hh          = (const float*)d_in[7];
    const float* lin_W         = (const float*)d_in[8];
    const float* lin_b         = (const float*)d_in[9];
    const float* ll_W          = (const float*)d_in[10];
    const float* ll_b          = (const float*)d_in[11];
    float* out = (float*)d_out;

    dim3 ggrid((GG + 63) / 64, (VV + 127) / 128);   // n fastest -> A slab L2 reuse
    // ncu captures launch index 3 -> lstm there (gemm runs first, dependency kept).
    gemm_P_kernel<<<ggrid, 256>>>(emb, W_ih, b_ih, b_hh);            // idx 0
    label_kernel<<<BB, 128>>>(label_word_id, emb, ll_W, ll_b);       // idx 1
    probe_kernel<<<1, 32>>>();                                       // idx 2
    lstm_kernel<<<BB / NB, LSTM_THREADS>>>(word_id, sen_len, W_hh);  // idx 3 (profiled)
    catch_kernel<<<BB, 128>>>(sen_len, lin_W, lin_b, out);           // idx 4
    scan_kernel<<<1, 192>>>(lin_b, out);                             // idx 5
}

// round 15
// speedup vs baseline: 1.4555x; 1.1447x over previous
#include <cuda_runtime.h>
#include <cuda_bf16.h>
#include <math.h>

// Problem dims
#define BB 1024
#define TT 128
#define EE 300
#define HH 100
#define GG 400     // 4*H
#define VV 50000
#define NB 8       // batches per LSTM CTA
#define NTILES 50  // GG/8 (permuted gate-interleaved layout)
#define KT16 7     // ceil(HH/16) bf16 k-tiles
#define LSTM_THREADS 576

// Scratch (device globals -- no allocation allowed)
// g_P is stored COLUMN-PERMUTED: permuted col p holds orig col (p&3)*100+(p>>2)
__device__ float g_P[VV * GG];
__device__ float g_out[BB * TT * HH]; // hidden states (52 MB)
__device__ float g_label[BB * HH];
__device__ float g_q[BB * 6];
__device__ float g_probe;

// ---------------- PTX helpers ----------------
__device__ __forceinline__ unsigned pack_bf16(float lo, float hi) {
    __nv_bfloat162 v = __floats2bfloat162_rn(lo, hi);
    return *reinterpret_cast<unsigned*>(&v);
}

__device__ __forceinline__ void mma_tf32(float* d, const unsigned* a, const unsigned* b) {
    asm volatile(
        "mma.sync.aligned.m16n8k8.row.col.f32.tf32.tf32.f32 "
        "{%0,%1,%2,%3}, {%4,%5,%6,%7}, {%8,%9}, {%0,%1,%2,%3};"
        : "+f"(d[0]), "+f"(d[1]), "+f"(d[2]), "+f"(d[3])
        : "r"(a[0]), "r"(a[1]), "r"(a[2]), "r"(a[3]), "r"(b[0]), "r"(b[1]));
}

// bf16 m16n8k16; A rows 8..15 are zero padding -> a1,a3 = 0. d[2],d[3] junk.
__device__ __forceinline__ void mma_bf16_half4(float* d, unsigned a0, unsigned a2,
                                               unsigned b0, unsigned b1) {
    asm volatile(
        "mma.sync.aligned.m16n8k16.row.col.f32.bf16.bf16.f32 "
        "{%0,%1,%2,%3}, {%4,%5,%6,%7}, {%8,%9}, {%0,%1,%2,%3};"
        : "+f"(d[0]), "+f"(d[1]), "+f"(d[2]), "+f"(d[3])
        : "r"(a0), "r"(0u), "r"(a2), "r"(0u), "r"(b0), "r"(b1));
}

// ldmatrix (tf32-as-b16 trick): 8x8 tf32 tile = rows of 4 tf32 (16B) is
// bit-identical to 8x16 b16; lane 4r+c gets element (r,c) -> tf32 frag map.
__device__ __forceinline__ void ldsm_x4(unsigned* r, unsigned addr) {
    asm volatile("ldmatrix.sync.aligned.m8n8.x4.shared.b16 {%0,%1,%2,%3}, [%4];"
        : "=r"(r[0]), "=r"(r[1]), "=r"(r[2]), "=r"(r[3]) : "r"(addr));
}

// HW tanh (sm_75+)
__device__ __forceinline__ float tanh_hw(float x) {
    float y;
    asm("tanh.approx.f32 %0, %1;" : "=f"(y) : "f"(x));
    return y;
}
__device__ __forceinline__ float sigm_hw(float x) {
    return fmaf(tanh_hw(0.5f * x), 0.5f, 0.5f);
}

// ---------------------------------------------------------------------------
// Kernel 1: P[v, p] = sum_e emb[v,e]*W_ih[orig(p),e] + bias[orig(p)]
// tf32 mma GEMM, 128x64 CTA tile, 128 threads, 4 warps of 64x32 tiles.
// B fragments via ldmatrix.x4 spanning 2 n-tiles -> matrix-unit reads/kt
// drop 128 -> 96 and ldmatrix op count drops ~2.6x (L1 was the binder).
// ---------------------------------------------------------------------------
#define A_STRIDE 20
#define B_STRIDE 20
#define NITER 19   // ceil(300/16)

__global__ void __launch_bounds__(128)
gemm_P_kernel(const float* __restrict__ emb,
              const float* __restrict__ W_ih,
              const float* __restrict__ b_ih,
              const float* __restrict__ b_hh) {
    __shared__ float As[2][128 * A_STRIDE];
    __shared__ float Bs[2][64 * B_STRIDE];

    const int m0 = blockIdx.y * 128;
    const int n0 = blockIdx.x * 64;   // permuted-column block
    const int tid = threadIdx.x;
    const int lane = tid & 31;
    const int wid = tid >> 5;         // 0..3
    const int warp_m = wid & 1;       // 64-row half
    const int warp_n = wid >> 1;      // 32-col half

    float acc[4][4][4];
#pragma unroll
    for (int mt = 0; mt < 4; mt++)
#pragma unroll
        for (int nt = 0; nt < 4; nt++)
#pragma unroll
            for (int c = 0; c < 4; c++) acc[mt][nt][c] = 0.f;

    // prefetch regs: A 4 x float4 (rows ar, ar+32, ar+64, ar+96), B 2 x float4
    float4 ra[4], rb[2];
    const int aq = tid & 3;           // k-quarter
    const int ar = tid >> 2;          // 0..31
    int bro[2], bqo[2];
#pragma unroll
    for (int i = 0; i < 2; i++) {
        int idx = tid + i * 128;      // 0..255
        bro[i] = idx >> 2;            // 0..63
        bqo[i] = idx & 3;
    }
    int bnorig[2];
#pragma unroll
    for (int i = 0; i < 2; i++) {
        int gn_p = n0 + bro[i];
        bnorig[i] = (gn_p & 3) * 100 + (gn_p >> 2);
    }

    auto loadAB = [&](int it) {
        int k0 = it * 16;
        int gk = k0 + aq * 4;
#pragma unroll
        for (int i = 0; i < 4; i++) {
            int gm = m0 + ar + i * 32;
            ra[i] = make_float4(0.f, 0.f, 0.f, 0.f);
            if (gm < VV && gk < EE)
                ra[i] = *reinterpret_cast<const float4*>(&emb[gm * EE + gk]);
        }
#pragma unroll
        for (int i = 0; i < 2; i++) {
            int gkb = k0 + bqo[i] * 4;
            rb[i] = make_float4(0.f, 0.f, 0.f, 0.f);
            if ((n0 + bro[i]) < GG && gkb < EE)
                rb[i] = *reinterpret_cast<const float4*>(&W_ih[bnorig[i] * EE + gkb]);
        }
    };

    loadAB(0);

    // ldmatrix lane components
    const int lr = lane & 7;
    const int lhalf = (lane >> 3) & 1;
    const int lkh = (lane >> 4) & 1;
    const int b_nt = lane >> 4;          // 0/1: n-tile within the x4
    const int b_kh = (lane >> 3) & 1;    // k-half
    const int b_r = lane & 7;

    for (int it = 0; it < NITER; it++) {
        const int buf = it & 1;
#pragma unroll
        for (int i = 0; i < 4; i++)
            *reinterpret_cast<float4*>(&As[buf][(ar + i * 32) * A_STRIDE + aq * 4]) = ra[i];
#pragma unroll
        for (int i = 0; i < 2; i++)
            *reinterpret_cast<float4*>(&Bs[buf][bro[i] * B_STRIDE + bqo[i] * 4]) = rb[i];
        __syncthreads();

        if (it + 1 < NITER) loadAB(it + 1);

#pragma unroll
        for (int kt = 0; kt < 2; kt++) {
            unsigned afr[4][4];
#pragma unroll
            for (int mt = 0; mt < 4; mt++) {
                int row = warp_m * 64 + mt * 16 + lhalf * 8 + lr;
                unsigned addr = (unsigned)__cvta_generic_to_shared(
                    &As[buf][row * A_STRIDE + lkh * 4]) + kt * 32;
                ldsm_x4(afr[mt], addr);
            }
            unsigned bfr[4][2];
#pragma unroll
            for (int g = 0; g < 2; g++) {
                int row = warp_n * 32 + g * 16 + b_nt * 8 + b_r;
                unsigned addr = (unsigned)__cvta_generic_to_shared(
                    &Bs[buf][row * B_STRIDE + b_kh * 4]) + kt * 32;
                unsigned r4[4];
                ldsm_x4(r4, addr);
                bfr[2 * g][0] = r4[0]; bfr[2 * g][1] = r4[1];
                bfr[2 * g + 1][0] = r4[2]; bfr[2 * g + 1][1] = r4[3];
            }
#pragma unroll
            for (int mt = 0; mt < 4; mt++)
#pragma unroll
                for (int nt = 0; nt < 4; nt++)
                    mma_tf32(acc[mt][nt], afr[mt], bfr[nt]);
        }
        __syncthreads();
    }

    // epilogue: bias (orig index) + contiguous float2 store at permuted cols
#pragma unroll
    for (int nt = 0; nt < 4; nt++) {
        int col = n0 + warp_n * 32 + nt * 8 + (lane & 3) * 2;   // permuted
        if (col >= GG) continue;
        int o0 = (col & 3) * 100 + (col >> 2);
        int o1 = ((col + 1) & 3) * 100 + ((col + 1) >> 2);
        float ba = b_ih[o0] + b_hh[o0];
        float bb = b_ih[o1] + b_hh[o1];
#pragma unroll
        for (int mt = 0; mt < 4; mt++) {
            int row0 = m0 + warp_m * 64 + mt * 16 + (lane >> 2);
            if (row0 < VV) {
                float2 v = make_float2(acc[mt][nt][0] + ba, acc[mt][nt][1] + bb);
                *reinterpret_cast<float2*>(&g_P[(size_t)row0 * GG + col]) = v;
            }
            int row1 = row0 + 8;
            if (row1 < VV) {
                float2 v = make_float2(acc[mt][nt][2] + ba, acc[mt][nt][3] + bb);
                *reinterpret_cast<float2*>(&g_P[(size_t)row1 * GG + col]) = v;
            }
        }
    }
}

// ---------------------------------------------------------------------------
// Kernel 2: label_vec[b] = emb[label_word_id[b]] @ ll_W^T + ll_b
// ---------------------------------------------------------------------------
__global__ void label_kernel(const int* __restrict__ label_word_id,
                             const float* __restrict__ emb,
                             const float* __restrict__ ll_W,
                             const float* __restrict__ ll_b) {
    __shared__ float row[EE];
    const int b = blockIdx.x;
    const int w = label_word_id[b];
    for (int e = threadIdx.x; e < EE; e += blockDim.x) row[e] = emb[w * EE + e];
    __syncthreads();
    const int j = threadIdx.x;
    if (j < HH) {
        float s = ll_b[j];
        const float* wr = &ll_W[j * EE];
        for (int e = 0; e < EE; e++) s += row[e] * wr[e];
        g_label[b * HH + j] = s;
    }
}

__global__ void probe_kernel() {
    if (threadIdx.x == 0) g_probe = 0.f;
}

// ---------------------------------------------------------------------------
// Kernel 3: LSTM recurrence on bf16 m16n8k16 (measured best structure).
// This round: g_last writes deleted (catch reads g_out[b, L-1] directly).
// ---------------------------------------------------------------------------
__global__ void __launch_bounds__(LSTM_THREADS, 1)
lstm_kernel(const int* __restrict__ word_id,
            const int* __restrict__ sen_len,
            const float* __restrict__ W_hh) {
    __shared__ unsigned Hf[2][KT16 * 64];
    __shared__ int rows[2][NB];

    const int tid = threadIdx.x;
    const int b0 = blockIdx.x * NB;
    const int lane = tid & 31;
    const int w = tid >> 5;
    const int nb = lane >> 2;
    const int cl2 = 2 * (lane & 3);

    const int ntc = (w == 12 || w == 13 || w == 16 || w == 17) ? 2 : 3;
    const int base = 3 * w - (w > 12) - (w > 13) - (w > 16) - (w > 17);

    // ---- one-time: ALL W_hh B-fragments into registers (bf16, permuted cols)
    unsigned Breg[3][KT16][2];
#pragma unroll
    for (int i = 0; i < 3; i++) {
        int nt = base + i;
        int n_perm = nt * 8 + (lane >> 2);
        int orig_n = (n_perm & 3) * 100 + (n_perm >> 2);
        const float* wr = &W_hh[orig_n * HH];
#pragma unroll
        for (int kt = 0; kt < KT16; kt++) {
            if (i < ntc) {
                int k0 = kt * 16 + (lane & 3) * 2;
                float l0 = (k0 < HH) ? wr[k0] : 0.f;
                float h0 = (k0 + 1 < HH) ? wr[k0 + 1] : 0.f;
                Breg[i][kt][0] = pack_bf16(l0, h0);
                int k8 = k0 + 8;
                float l1 = (k8 < HH) ? wr[k8] : 0.f;
                float h1 = (k8 + 1 < HH) ? wr[k8 + 1] : 0.f;
                Breg[i][kt][1] = pack_bf16(l1, h1);
            } else {
                Breg[i][kt][0] = 0u;
                Breg[i][kt][1] = 0u;
            }
        }
    }

    // zero BOTH Hf buffers (k-pad 100..111 must stay zero forever)
    for (int idx = tid; idx < 2 * KT16 * 64; idx += LSTM_THREADS)
        (&Hf[0][0])[idx] = 0u;
    if (tid < NB)
        rows[0][tid] = word_id[(b0 + tid) * TT];

    // ---- hoist loop-invariant activation addressing ----
    const bool odd = (lane & 1);
    const int jsel = (lane >> 1) & 1;
    bool  wrv[2];
    int   hfhw[2];
    float* outp[2];
#pragma unroll
    for (int bundle = 0; bundle < 2; bundle++) {
        const int iA = (bundle == 0) ? 0 : 2;
        const int iB = (bundle == 0) ? 1 : 2;
        int nt = base + (odd ? iB : iA);
        int j = 2 * nt + jsel;
        wrv[bundle] = !(iA == iB && odd);
        int kt = j >> 4, half = (j >> 3) & 1, c = (j & 7) >> 1, hi = j & 1;
        hfhw[bundle] = (kt * 64 + (nb * 4 + c) * 2 + half) * 2 + hi;
        outp[bundle] = &g_out[((size_t)(b0 + nb) * TT) * HH + j];
    }
    __syncthreads();

    float cst[2] = {0.f, 0.f};

    for (int t = 0; t < TT; t++) {
        const int buf = t & 1;

        float2 pv[3];
        {
            const float* Prow = &g_P[(size_t)rows[buf][nb] * GG];
            pv[0] = *reinterpret_cast<const float2*>(&Prow[(base + 0) * 8 + cl2]);
            pv[1] = *reinterpret_cast<const float2*>(&Prow[(base + 1) * 8 + cl2]);
            if (ntc == 3)
                pv[2] = *reinterpret_cast<const float2*>(&Prow[(base + 2) * 8 + cl2]);
        }

        float acc[3][4];
#pragma unroll
        for (int i = 0; i < 3; i++) {
            acc[i][0] = 0.f; acc[i][1] = 0.f; acc[i][2] = 0.f; acc[i][3] = 0.f;
        }

#pragma unroll
        for (int kt = 0; kt < KT16; kt++) {
            uint2 hv = *reinterpret_cast<const uint2*>(&Hf[buf][kt * 64 + lane * 2]);
            mma_bf16_half4(acc[0], hv.x, hv.y, Breg[0][kt][0], Breg[0][kt][1]);
            mma_bf16_half4(acc[1], hv.x, hv.y, Breg[1][kt][0], Breg[1][kt][1]);
            if (ntc == 3)
                mma_bf16_half4(acc[2], hv.x, hv.y, Breg[2][kt][0], Breg[2][kt][1]);
        }
        float r[3][2];
        r[0][0] = acc[0][0] + pv[0].x;  r[0][1] = acc[0][1] + pv[0].y;
        r[1][0] = acc[1][0] + pv[1].x;  r[1][1] = acc[1][1] + pv[1].y;
        if (ntc == 3) { r[2][0] = acc[2][0] + pv[2].x;  r[2][1] = acc[2][1] + pv[2].y; }

#pragma unroll
        for (int bundle = 0; bundle < 2; bundle++) {
            if (bundle == 1 && ntc < 3) break;
            const int iA = (bundle == 0) ? 0 : 2;
            const int iB = (bundle == 0) ? 1 : 2;
            float xA0 = __shfl_xor_sync(0xffffffffu, r[iA][0], 1);
            float xA1 = __shfl_xor_sync(0xffffffffu, r[iA][1], 1);
            float xB0 = __shfl_xor_sync(0xffffffffu, r[iB][0], 1);
            float xB1 = __shfl_xor_sync(0xffffffffu, r[iB][1], 1);
            float gi = odd ? xB0 : r[iA][0];
            float gf = odd ? xB1 : r[iA][1];
            float gg = odd ? r[iB][0] : xA0;
            float go = odd ? r[iB][1] : xA1;

            float si = sigm_hw(gi);
            float sf = sigm_hw(gf);
            float so = sigm_hw(go);
            float sg = tanh_hw(gg);
            float cv = sf * cst[bundle] + si * sg;
            cst[bundle] = cv;
            float h = so * tanh_hw(cv);

            if (wrv[bundle]) {
                reinterpret_cast<__nv_bfloat16*>(&Hf[1 - buf][0])[hfhw[bundle]] =
                    __float2bfloat16_rn(h);
                outp[bundle][0] = h;
            }
        }
        outp[0] += HH;
        outp[1] += HH;

        if (tid < NB && t + 1 < TT)
            rows[1 - buf][tid] = word_id[(b0 + tid) * TT + t + 1];
        __syncthreads();
    }
}

// ---------------------------------------------------------------------------
// Kernel 4: per-batch epilogue: scores, top-4, pos, per_neg, out_f, l_rep, q.
// last hidden state read directly from g_out[b, L-1] (g_last removed).
// ---------------------------------------------------------------------------
__global__ void catch_kernel(const int* __restrict__ sen_len,
                             const float* __restrict__ lin_W,
                             const float* __restrict__ lin_b,
                             float* __restrict__ dout) {
    __shared__ float label_s[HH];
    __shared__ float last_s[HH];
    __shared__ float scores[TT];
    __shared__ float red_v[TT];
    __shared__ int   red_i[TT];
    __shared__ float topv[4];
    __shared__ int   topi[4];
    __shared__ float pos_s[HH];
    __shared__ float pneg_s[HH];

    const int b = blockIdx.x;
    const int tid = threadIdx.x;
    const int L = sen_len[b];

    if (tid < HH) {
        label_s[tid] = g_label[b * HH + tid];
        last_s[tid]  = g_out[((size_t)b * TT + (L - 1)) * HH + tid];
    }
    __syncthreads();

    {
        float s;
        if (tid < L) {
            s = 0.f;
            const float* o = &g_out[((size_t)b * TT + tid) * HH];
            for (int j = 0; j < HH; j++) s += o[j] * label_s[j];
        } else {
            s = -1e30f;
        }
        scores[tid] = s;
    }
    __syncthreads();

    for (int k = 0; k < 4; k++) {
        red_v[tid] = scores[tid];
        red_i[tid] = tid;
        __syncthreads();
        for (int off = TT / 2; off > 0; off >>= 1) {
            if (tid < off) {
                float v2 = red_v[tid + off];
                int   i2 = red_i[tid + off];
                if (v2 > red_v[tid] || (v2 == red_v[tid] && i2 < red_i[tid])) {
                    red_v[tid] = v2;
                    red_i[tid] = i2;
                }
            }
            __syncthreads();
        }
        if (tid == 0) {
            topv[k] = red_v[0];
            topi[k] = red_i[0];
            scores[red_i[0]] = -1e30f;
        }
        __syncthreads();
    }

    if (tid < HH) {
        float p = 0.f;
#pragma unroll
        for (int k = 0; k < 4; k++)
            p += g_out[((size_t)b * TT + topi[k]) * HH + tid] * topv[k];
        pos_s[tid] = p;

        float s = 0.f;
        int i0 = topi[0], i1 = topi[1], i2 = topi[2], i3 = topi[3];
        for (int t = 0; t < L; t++) {
            if (t == i0 || t == i1 || t == i2 || t == i3) continue;
            s += g_out[((size_t)b * TT + t) * HH + tid];
        }
        pneg_s[tid] = s;
    }
    __syncthreads();

    if (tid < 6) {
        float bo = lin_b[tid];
        float o = bo, l = bo, q = 0.f;
        const float* wv = &lin_W[tid * HH];
        for (int j = 0; j < HH; j++) {
            float wj = wv[j];
            o += last_s[j] * wj;
            l += pos_s[j] * wj;
            q += pneg_s[j] * wj;
        }
        dout[b * 6 + tid] = o;
        dout[BB * 6 + b * 6 + tid] = l;
        g_q[b * 6 + tid] = q;
    }
}

// ---------------------------------------------------------------------------
// Kernel 5: r_rep = cumsum over batch of q + lin_b (warp-parallel scan).
// ---------------------------------------------------------------------------
__global__ void scan_kernel(const float* __restrict__ lin_b,
                            float* __restrict__ dout) {
    const int w = threadIdx.x >> 5;
    const int l = threadIdx.x & 31;
    if (w >= 6) return;
    float run = lin_b[w];
    for (int c0 = 0; c0 < BB; c0 += 32) {
        float v = g_q[(c0 + l) * 6 + w];
#pragma unroll
        for (int off = 1; off < 32; off <<= 1) {
            float u = __shfl_up_sync(0xffffffff, v, off);
            if (l >= off) v += u;
        }
        dout[2 * BB * 6 + (c0 + l) * 6 + w] = run + v;
        run += __shfl_sync(0xffffffff, v, 31);
    }
}

// ---------------------------------------------------------------------------
extern "C" void kernel_launch(void* const* d_in, const int* in_sizes, int n_in,
                              void* d_out, int out_size) {
    const int*   word_id       = (const int*)d_in[0];
    const int*   sen_len       = (const int*)d_in[1];
    const int*   label_word_id = (const int*)d_in[2];
    const float* emb           = (const float*)d_in[3];
    const float* W_ih          = (const float*)d_in[4];
    const float* W_hh          = (const float*)d_in[5];
    const float* b_ih          = (const float*)d_in[6];
    const float* b_hh          = (const float*)d_in[7];
    const float* lin_W         = (const float*)d_in[8];
    const float* lin_b         = (const float*)d_in[9];
    const float* ll_W          = (const float*)d_in[10];
    const float* ll_b          = (const float*)d_in[11];
    float* out = (float*)d_out;

    dim3 ggrid((GG + 63) / 64, (VV + 127) / 128);   // n fastest -> A slab L2 reuse
    // ncu captures launch index 3 -> gemm there to verify the 64x32 tile fix.
    probe_kernel<<<1, 32>>>();                                       // idx 0
    probe_kernel<<<1, 32>>>();                                       // idx 1
    probe_kernel<<<1, 32>>>();                                       // idx 2
    gemm_P_kernel<<<ggrid, 128>>>(emb, W_ih, b_ih, b_hh);            // idx 3 (profiled)
    label_kernel<<<BB, 128>>>(label_word_id, emb, ll_W, ll_b);       // idx 4
    lstm_kernel<<<BB / NB, LSTM_THREADS>>>(word_id, sen_len, W_hh);  // idx 5
    catch_kernel<<<BB, 128>>>(sen_len, lin_W, lin_b, out);           // idx 6
    scan_kernel<<<1, 192>>>(lin_b, out);                             // idx 7
}

// round 16
// speedup vs baseline: 1.5150x; 1.0408x over previous
#include <cuda_runtime.h>
#include <cuda_bf16.h>
#include <math.h>

// Problem dims
#define BB 1024
#define TT 128
#define EE 300
#define HH 100
#define GG 400     // 4*H
#define VV 50000
#define NB 8       // batches per LSTM CTA
#define NTILES 50  // GG/8 (permuted gate-interleaved layout)
#define KT16 7     // ceil(HH/16) bf16 k-tiles
#define LSTM_THREADS 800   // 25 warps x 2 tiles = 50 tiles, perfectly balanced

// Scratch (device globals -- no allocation allowed)
// g_P is stored COLUMN-PERMUTED: permuted col p holds orig col (p&3)*100+(p>>2)
__device__ float g_P[VV * GG];
__device__ float g_out[BB * TT * HH]; // hidden states (52 MB)
__device__ float g_label[BB * HH];
__device__ float g_q[BB * 6];
__device__ float g_probe;

// ---------------- PTX helpers ----------------
__device__ __forceinline__ unsigned pack_bf16(float lo, float hi) {
    __nv_bfloat162 v = __floats2bfloat162_rn(lo, hi);
    return *reinterpret_cast<unsigned*>(&v);
}

__device__ __forceinline__ void mma_tf32(float* d, const unsigned* a, const unsigned* b) {
    asm volatile(
        "mma.sync.aligned.m16n8k8.row.col.f32.tf32.tf32.f32 "
        "{%0,%1,%2,%3}, {%4,%5,%6,%7}, {%8,%9}, {%0,%1,%2,%3};"
        : "+f"(d[0]), "+f"(d[1]), "+f"(d[2]), "+f"(d[3])
        : "r"(a[0]), "r"(a[1]), "r"(a[2]), "r"(a[3]), "r"(b[0]), "r"(b[1]));
}

// bf16 m16n8k16; A rows 8..15 are zero padding -> a1,a3 = 0. d[2],d[3] junk.
__device__ __forceinline__ void mma_bf16_half4(float* d, unsigned a0, unsigned a2,
                                               unsigned b0, unsigned b1) {
    asm volatile(
        "mma.sync.aligned.m16n8k16.row.col.f32.bf16.bf16.f32 "
        "{%0,%1,%2,%3}, {%4,%5,%6,%7}, {%8,%9}, {%0,%1,%2,%3};"
        : "+f"(d[0]), "+f"(d[1]), "+f"(d[2]), "+f"(d[3])
        : "r"(a0), "r"(0u), "r"(a2), "r"(0u), "r"(b0), "r"(b1));
}

// ldmatrix (tf32-as-b16 trick): 8x8 tf32 tile = rows of 4 tf32 (16B) is
// bit-identical to 8x16 b16; lane 4r+c gets element (r,c) -> tf32 frag map.
__device__ __forceinline__ void ldsm_x4(unsigned* r, unsigned addr) {
    asm volatile("ldmatrix.sync.aligned.m8n8.x4.shared.b16 {%0,%1,%2,%3}, [%4];"
        : "=r"(r[0]), "=r"(r[1]), "=r"(r[2]), "=r"(r[3]) : "r"(addr));
}

// HW tanh (sm_75+)
__device__ __forceinline__ float tanh_hw(float x) {
    float y;
    asm("tanh.approx.f32 %0, %1;" : "=f"(y) : "f"(x));
    return y;
}
__device__ __forceinline__ float sigm_hw(float x) {
    return fmaf(tanh_hw(0.5f * x), 0.5f, 0.5f);
}

// ---------------------------------------------------------------------------
// Kernel 1: P[v, p] = sum_e emb[v,e]*W_ih[orig(p),e] + bias[orig(p)]
// (unchanged from round 15 -- measured 140us, near layout floor)
// ---------------------------------------------------------------------------
#define A_STRIDE 20
#define B_STRIDE 20
#define NITER 19   // ceil(300/16)

__global__ void __launch_bounds__(128)
gemm_P_kernel(const float* __restrict__ emb,
              const float* __restrict__ W_ih,
              const float* __restrict__ b_ih,
              const float* __restrict__ b_hh) {
    __shared__ float As[2][128 * A_STRIDE];
    __shared__ float Bs[2][64 * B_STRIDE];

    const int m0 = blockIdx.y * 128;
    const int n0 = blockIdx.x * 64;   // permuted-column block
    const int tid = threadIdx.x;
    const int lane = tid & 31;
    const int wid = tid >> 5;         // 0..3
    const int warp_m = wid & 1;       // 64-row half
    const int warp_n = wid >> 1;      // 32-col half

    float acc[4][4][4];
#pragma unroll
    for (int mt = 0; mt < 4; mt++)
#pragma unroll
        for (int nt = 0; nt < 4; nt++)
#pragma unroll
            for (int c = 0; c < 4; c++) acc[mt][nt][c] = 0.f;

    float4 ra[4], rb[2];
    const int aq = tid & 3;
    const int ar = tid >> 2;
    int bro[2], bqo[2];
#pragma unroll
    for (int i = 0; i < 2; i++) {
        int idx = tid + i * 128;
        bro[i] = idx >> 2;
        bqo[i] = idx & 3;
    }
    int bnorig[2];
#pragma unroll
    for (int i = 0; i < 2; i++) {
        int gn_p = n0 + bro[i];
        bnorig[i] = (gn_p & 3) * 100 + (gn_p >> 2);
    }

    auto loadAB = [&](int it) {
        int k0 = it * 16;
        int gk = k0 + aq * 4;
#pragma unroll
        for (int i = 0; i < 4; i++) {
            int gm = m0 + ar + i * 32;
            ra[i] = make_float4(0.f, 0.f, 0.f, 0.f);
            if (gm < VV && gk < EE)
                ra[i] = *reinterpret_cast<const float4*>(&emb[gm * EE + gk]);
        }
#pragma unroll
        for (int i = 0; i < 2; i++) {
            int gkb = k0 + bqo[i] * 4;
            rb[i] = make_float4(0.f, 0.f, 0.f, 0.f);
            if ((n0 + bro[i]) < GG && gkb < EE)
                rb[i] = *reinterpret_cast<const float4*>(&W_ih[bnorig[i] * EE + gkb]);
        }
    };

    loadAB(0);

    const int lr = lane & 7;
    const int lhalf = (lane >> 3) & 1;
    const int lkh = (lane >> 4) & 1;
    const int b_nt = lane >> 4;
    const int b_kh = (lane >> 3) & 1;
    const int b_r = lane & 7;

    for (int it = 0; it < NITER; it++) {
        const int buf = it & 1;
#pragma unroll
        for (int i = 0; i < 4; i++)
            *reinterpret_cast<float4*>(&As[buf][(ar + i * 32) * A_STRIDE + aq * 4]) = ra[i];
#pragma unroll
        for (int i = 0; i < 2; i++)
            *reinterpret_cast<float4*>(&Bs[buf][bro[i] * B_STRIDE + bqo[i] * 4]) = rb[i];
        __syncthreads();

        if (it + 1 < NITER) loadAB(it + 1);

#pragma unroll
        for (int kt = 0; kt < 2; kt++) {
            unsigned afr[4][4];
#pragma unroll
            for (int mt = 0; mt < 4; mt++) {
                int row = warp_m * 64 + mt * 16 + lhalf * 8 + lr;
                unsigned addr = (unsigned)__cvta_generic_to_shared(
                    &As[buf][row * A_STRIDE + lkh * 4]) + kt * 32;
                ldsm_x4(afr[mt], addr);
            }
            unsigned bfr[4][2];
#pragma unroll
            for (int g = 0; g < 2; g++) {
                int row = warp_n * 32 + g * 16 + b_nt * 8 + b_r;
                unsigned addr = (unsigned)__cvta_generic_to_shared(
                    &Bs[buf][row * B_STRIDE + b_kh * 4]) + kt * 32;
                unsigned r4[4];
                ldsm_x4(r4, addr);
                bfr[2 * g][0] = r4[0]; bfr[2 * g][1] = r4[1];
                bfr[2 * g + 1][0] = r4[2]; bfr[2 * g + 1][1] = r4[3];
            }
#pragma unroll
            for (int mt = 0; mt < 4; mt++)
#pragma unroll
                for (int nt = 0; nt < 4; nt++)
                    mma_tf32(acc[mt][nt], afr[mt], bfr[nt]);
        }
        __syncthreads();
    }

#pragma unroll
    for (int nt = 0; nt < 4; nt++) {
        int col = n0 + warp_n * 32 + nt * 8 + (lane & 3) * 2;   // permuted
        if (col >= GG) continue;
        int o0 = (col & 3) * 100 + (col >> 2);
        int o1 = ((col + 1) & 3) * 100 + ((col + 1) >> 2);
        float ba = b_ih[o0] + b_hh[o0];
        float bb = b_ih[o1] + b_hh[o1];
#pragma unroll
        for (int mt = 0; mt < 4; mt++) {
            int row0 = m0 + warp_m * 64 + mt * 16 + (lane >> 2);
            if (row0 < VV) {
                float2 v = make_float2(acc[mt][nt][0] + ba, acc[mt][nt][1] + bb);
                *reinterpret_cast<float2*>(&g_P[(size_t)row0 * GG + col]) = v;
            }
            int row1 = row0 + 8;
            if (row1 < VV) {
                float2 v = make_float2(acc[mt][nt][2] + ba, acc[mt][nt][3] + bb);
                *reinterpret_cast<float2*>(&g_P[(size_t)row1 * GG + col]) = v;
            }
        }
    }
}

// ---------------------------------------------------------------------------
// Kernel 2: label_vec[b] = emb[label_word_id[b]] @ ll_W^T + ll_b
// ---------------------------------------------------------------------------
__global__ void label_kernel(const int* __restrict__ label_word_id,
                             const float* __restrict__ emb,
                             const float* __restrict__ ll_W,
                             const float* __restrict__ ll_b) {
    __shared__ float row[EE];
    const int b = blockIdx.x;
    const int w = label_word_id[b];
    for (int e = threadIdx.x; e < EE; e += blockDim.x) row[e] = emb[w * EE + e];
    __syncthreads();
    const int j = threadIdx.x;
    if (j < HH) {
        float s = ll_b[j];
        const float* wr = &ll_W[j * EE];
        for (int e = 0; e < EE; e++) s += row[e] * wr[e];
        g_label[b * HH + j] = s;
    }
}

__global__ void probe_kernel() {
    if (threadIdx.x == 0) g_probe = 0.f;
}

// ---------------------------------------------------------------------------
// Kernel 3: LSTM recurrence on bf16 m16n8k16. 128 CTAs x NB=8.
// THIS ROUND: 800 threads = 25 warps x 2 tiles = 50 tiles exactly.
//  - every warp identical: 2 tiles, 14 MMAs, ONE activation bundle (4 shfl)
//  - per-warp instruction stream ~halved; warps/SMSP 4.5 -> 6.25
//  - Breg 28 regs; total live ~60 < 80 cap (800thr) -> no spills
// ---------------------------------------------------------------------------
__global__ void __launch_bounds__(LSTM_THREADS, 1)
lstm_kernel(const int* __restrict__ word_id,
            const int* __restrict__ sen_len,
            const float* __restrict__ W_hh) {
    __shared__ unsigned Hf[2][KT16 * 64];
    __shared__ int rows[2][NB];

    const int tid = threadIdx.x;
    const int b0 = blockIdx.x * NB;
    const int lane = tid & 31;
    const int w = tid >> 5;           // 0..24
    const int nb = lane >> 2;
    const int cl2 = 2 * (lane & 3);
    const int base = 2 * w;           // tiles {2w, 2w+1}

    // ---- one-time: W_hh B-fragments into registers (bf16, permuted cols) ----
    unsigned Breg[2][KT16][2];
#pragma unroll
    for (int i = 0; i < 2; i++) {
        int nt = base + i;
        int n_perm = nt * 8 + (lane >> 2);
        int orig_n = (n_perm & 3) * 100 + (n_perm >> 2);
        const float* wr = &W_hh[orig_n * HH];
#pragma unroll
        for (int kt = 0; kt < KT16; kt++) {
            int k0 = kt * 16 + (lane & 3) * 2;
            float l0 = (k0 < HH) ? wr[k0] : 0.f;
            float h0 = (k0 + 1 < HH) ? wr[k0 + 1] : 0.f;
            Breg[i][kt][0] = pack_bf16(l0, h0);
            int k8 = k0 + 8;
            float l1 = (k8 < HH) ? wr[k8] : 0.f;
            float h1 = (k8 + 1 < HH) ? wr[k8 + 1] : 0.f;
            Breg[i][kt][1] = pack_bf16(l1, h1);
        }
    }

    // zero BOTH Hf buffers (k-pad 100..111 must stay zero forever)
    for (int idx = tid; idx < 2 * KT16 * 64; idx += LSTM_THREADS)
        (&Hf[0][0])[idx] = 0u;
    if (tid < NB)
        rows[0][tid] = word_id[(b0 + tid) * TT];

    // ---- hoisted activation addressing (one bundle: tiles 0,1) ----
    const bool odd = (lane & 1);
    const int jsel = (lane >> 1) & 1;
    const int nt_j = base + (odd ? 1 : 0);
    const int j = 2 * nt_j + jsel;
    const int ktj = j >> 4, halfj = (j >> 3) & 1, cj = (j & 7) >> 1, hij = j & 1;
    const int hfhw = (ktj * 64 + (nb * 4 + cj) * 2 + halfj) * 2 + hij;
    float* outp = &g_out[((size_t)(b0 + nb) * TT) * HH + j];
    __syncthreads();

    float cst = 0.f;

    for (int t = 0; t < TT; t++) {
        const int buf = t & 1;

        float2 pv0, pv1;
        {
            const float* Prow = &g_P[(size_t)rows[buf][nb] * GG];
            pv0 = *reinterpret_cast<const float2*>(&Prow[(base + 0) * 8 + cl2]);
            pv1 = *reinterpret_cast<const float2*>(&Prow[(base + 1) * 8 + cl2]);
        }

        float acc[2][4];
#pragma unroll
        for (int i = 0; i < 2; i++) {
            acc[i][0] = 0.f; acc[i][1] = 0.f; acc[i][2] = 0.f; acc[i][3] = 0.f;
        }

#pragma unroll
        for (int kt = 0; kt < KT16; kt++) {
            uint2 hv = *reinterpret_cast<const uint2*>(&Hf[buf][kt * 64 + lane * 2]);
            mma_bf16_half4(acc[0], hv.x, hv.y, Breg[0][kt][0], Breg[0][kt][1]);
            mma_bf16_half4(acc[1], hv.x, hv.y, Breg[1][kt][0], Breg[1][kt][1]);
        }
        float r0x = acc[0][0] + pv0.x, r0y = acc[0][1] + pv0.y;
        float r1x = acc[1][0] + pv1.x, r1y = acc[1][1] + pv1.y;

        // assemble (i,f,g,o) for this lane's j via one xor(1) exchange
        float xA0 = __shfl_xor_sync(0xffffffffu, r0x, 1);
        float xA1 = __shfl_xor_sync(0xffffffffu, r0y, 1);
        float xB0 = __shfl_xor_sync(0xffffffffu, r1x, 1);
        float xB1 = __shfl_xor_sync(0xffffffffu, r1y, 1);
        float gi = odd ? xB0 : r0x;
        float gf = odd ? xB1 : r0y;
        float gg = odd ? r1x : xA0;
        float go = odd ? r1y : xA1;

        float si = sigm_hw(gi);
        float sf = sigm_hw(gf);
        float so = sigm_hw(go);
        float sg = tanh_hw(gg);
        float cv = sf * cst + si * sg;
        cst = cv;
        float h = so * tanh_hw(cv);

        reinterpret_cast<__nv_bfloat16*>(&Hf[1 - buf][0])[hfhw] =
            __float2bfloat16_rn(h);
        outp[0] = h;
        outp += HH;

        if (tid < NB && t + 1 < TT)
            rows[1 - buf][tid] = word_id[(b0 + tid) * TT + t + 1];
        __syncthreads();
    }
}

// ---------------------------------------------------------------------------
// Kernel 4: per-batch epilogue: scores, top-4, pos, per_neg, out_f, l_rep, q.
// ---------------------------------------------------------------------------
__global__ void catch_kernel(const int* __restrict__ sen_len,
                             const float* __restrict__ lin_W,
                             const float* __restrict__ lin_b,
                             float* __restrict__ dout) {
    __shared__ float label_s[HH];
    __shared__ float last_s[HH];
    __shared__ float scores[TT];
    __shared__ float red_v[TT];
    __shared__ int   red_i[TT];
    __shared__ float topv[4];
    __shared__ int   topi[4];
    __shared__ float pos_s[HH];
    __shared__ float pneg_s[HH];

    const int b = blockIdx.x;
    const int tid = threadIdx.x;
    const int L = sen_len[b];

    if (tid < HH) {
        label_s[tid] = g_label[b * HH + tid];
        last_s[tid]  = g_out[((size_t)b * TT + (L - 1)) * HH + tid];
    }
    __syncthreads();

    {
        float s;
        if (tid < L) {
            s = 0.f;
            const float* o = &g_out[((size_t)b * TT + tid) * HH];
            for (int j = 0; j < HH; j++) s += o[j] * label_s[j];
        } else {
            s = -1e30f;
        }
        scores[tid] = s;
    }
    __syncthreads();

    for (int k = 0; k < 4; k++) {
        red_v[tid] = scores[tid];
        red_i[tid] = tid;
        __syncthreads();
        for (int off = TT / 2; off > 0; off >>= 1) {
            if (tid < off) {
                float v2 = red_v[tid + off];
                int   i2 = red_i[tid + off];
                if (v2 > red_v[tid] || (v2 == red_v[tid] && i2 < red_i[tid])) {
                    red_v[tid] = v2;
                    red_i[tid] = i2;
                }
            }
            __syncthreads();
        }
        if (tid == 0) {
            topv[k] = red_v[0];
            topi[k] = red_i[0];
            scores[red_i[0]] = -1e30f;
        }
        __syncthreads();
    }

    if (tid < HH) {
        float p = 0.f;
#pragma unroll
        for (int k = 0; k < 4; k++)
            p += g_out[((size_t)b * TT + topi[k]) * HH + tid] * topv[k];
        pos_s[tid] = p;

        float s = 0.f;
        int i0 = topi[0], i1 = topi[1], i2 = topi[2], i3 = topi[3];
        for (int t = 0; t < L; t++) {
            if (t == i0 || t == i1 || t == i2 || t == i3) continue;
            s += g_out[((size_t)b * TT + t) * HH + tid];
        }
        pneg_s[tid] = s;
    }
    __syncthreads();

    if (tid < 6) {
        float bo = lin_b[tid];
        float o = bo, l = bo, q = 0.f;
        const float* wv = &lin_W[tid * HH];
        for (int j = 0; j < HH; j++) {
            float wj = wv[j];
            o += last_s[j] * wj;
            l += pos_s[j] * wj;
            q += pneg_s[j] * wj;
        }
        dout[b * 6 + tid] = o;
        dout[BB * 6 + b * 6 + tid] = l;
        g_q[b * 6 + tid] = q;
    }
}

// ---------------------------------------------------------------------------
// Kernel 5: r_rep = cumsum over batch of q + lin_b (warp-parallel scan).
// ---------------------------------------------------------------------------
__global__ void scan_kernel(const float* __restrict__ lin_b,
                            float* __restrict__ dout) {
    const int w = threadIdx.x >> 5;
    const int l = threadIdx.x & 31;
    if (w >= 6) return;
    float run = lin_b[w];
    for (int c0 = 0; c0 < BB; c0 += 32) {
        float v = g_q[(c0 + l) * 6 + w];
#pragma unroll
        for (int off = 1; off < 32; off <<= 1) {
            float u = __shfl_up_sync(0xffffffff, v, off);
            if (l >= off) v += u;
        }
        dout[2 * BB * 6 + (c0 + l) * 6 + w] = run + v;
        run += __shfl_sync(0xffffffff, v, 31);
    }
}

// ---------------------------------------------------------------------------
extern "C" void kernel_launch(void* const* d_in, const int* in_sizes, int n_in,
                              void* d_out, int out_size) {
    const int*   word_id       = (const int*)d_in[0];
    const int*   sen_len       = (const int*)d_in[1];
    const int*   label_word_id = (const int*)d_in[2];
    const float* emb           = (const float*)d_in[3];
    const float* W_ih          = (const float*)d_in[4];
    const float* W_hh          = (const float*)d_in[5];
    const float* b_ih          = (const float*)d_in[6];
    const float* b_hh          = (const float*)d_in[7];
    const float* lin_W         = (const float*)d_in[8];
    const float* lin_b         = (const float*)d_in[9];
    const float* ll_W          = (const float*)d_in[10];
    const float* ll_b          = (const float*)d_in[11];
    float* out = (float*)d_out;

    dim3 ggrid((GG + 63) / 64, (VV + 127) / 128);   // n fastest -> A slab L2 reuse
    // ncu captures launch index 3 -> lstm there (gemm runs first, dependency kept).
    gemm_P_kernel<<<ggrid, 128>>>(emb, W_ih, b_ih, b_hh);            // idx 0
    label_kernel<<<BB, 128>>>(label_word_id, emb, ll_W, ll_b);       // idx 1
    probe_kernel<<<1, 32>>>();                                       // idx 2
    lstm_kernel<<<BB / NB, LSTM_THREADS>>>(word_id, sen_len, W_hh);  // idx 3 (profiled)
    catch_kernel<<<BB, 128>>>(sen_len, lin_W, lin_b, out);           // idx 4
    scan_kernel<<<1, 192>>>(lin_b, out);                             // idx 5
}